// round 3
// baseline (speedup 1.0000x reference)
#include <cuda_runtime.h>
#include <cstdint>

// Problem constants
#define N_TOK   8192
#define DIM     4096
#define N_EXP   64
#define TOPK    2
#define CAP     160           // ceil(1.25 * 8192 / 64)
#define NEC     ((size_t)N_TOK * N_EXP * CAP)   // 83,886,080

// Scratch (device globals; no allocation allowed)
__device__ int   g_topk_idx[N_TOK * TOPK];
__device__ float g_topk_val[N_TOK * TOPK];
__device__ int   g_counts[N_EXP];
__device__ float g_colsum[N_EXP];

// packed fp32x2 FMA (sm_103a FFMA2): d.lo += a.lo*b.lo, d.hi += a.hi*b.hi
__device__ __forceinline__ void fma2(unsigned long long& d,
                                     unsigned long long a,
                                     unsigned long long b) {
    asm("fma.rn.f32x2 %0, %1, %2, %0;" : "+l"(d) : "l"(a), "l"(b));
}
__device__ __forceinline__ float ull_lo(unsigned long long a) {
    return __uint_as_float((unsigned)(a & 0xffffffffu));
}
__device__ __forceinline__ float ull_hi(unsigned long long a) {
    return __uint_as_float((unsigned)(a >> 32));
}

// ---------------------------------------------------------------------------
// Kernel 1: GEMM (logits = x @ gate_w^T) + softmax (probs) + top-2.
// Grid 128 x 128 threads. Block tile: 64 rows x 64 experts.
// Per-thread tile: 8 rows x 4 cols (32 accumulators as 16 f32x2 k-split pairs).
// FFMA2:LDS.128 ratio 64:12 per k4 -> crossbar demand ~109us chipwide (was 189).
// Double-buffered smem, ONE __syncthreads per 32-wide K chunk.
// ---------------------------------------------------------------------------
__global__ __launch_bounds__(128)
void gemm_topk_kernel(const float* __restrict__ x,
                      const float* __restrict__ gw,
                      float* __restrict__ probs_out) {
    __shared__ float smem[8192];         // 32KB: [buf0: X 2048 | W 2048][buf1: ...]

    const int tid = threadIdx.x;
    const int rowBase = blockIdx.x * 64;
    const int rg = tid & 7;              // 8 row-groups of 8 rows
    const int cg = tid >> 3;             // 16 col-groups of 4 cols
    const int row0 = rg * 8;
    const int c0 = cg * 4;
    const int aswz = rg << 2;            // (row>>3)&7 == rg for this thread's rows

    const float* xg = x + (size_t)rowBase * DIM;

    // staging: 4 float4 per thread per matrix per chunk
    int xoff[4], woff[4], gidx[4];
#pragma unroll
    for (int j = 0; j < 4; j++) {
        const int f = tid + j * 128;     // 0..511 float4 slots
        const int r = f >> 3;            // row 0..63
        const int kq = f & 7;            // 16B slot within 128B row
        xoff[j] = (r * 32 + kq * 4) ^ (((r >> 3) & 7) << 2);  // swizzled X
        woff[j] = r * 32 + kq * 4;                            // W unswizzled (reads broadcast)
        gidx[j] = r * DIM + kq * 4;
    }

    unsigned long long acc[8][4];
#pragma unroll
    for (int r = 0; r < 8; r++)
#pragma unroll
        for (int c = 0; c < 4; c++) acc[r][c] = 0ull;

    float4 xr[4], wr[4];
#pragma unroll
    for (int j = 0; j < 4; j++) {        // prologue: chunk 0
        xr[j] = *(const float4*)&xg[gidx[j]];
        wr[j] = *(const float4*)&gw[gidx[j]];
    }

#pragma unroll 1
    for (int kc = 0; kc < 128; kc++) {
        float* Xb = smem + (kc & 1) * 4096;
        float* Wb = Xb + 2048;
#pragma unroll
        for (int j = 0; j < 4; j++) {
            *(float4*)&Xb[xoff[j]] = xr[j];
            *(float4*)&Wb[woff[j]] = wr[j];
        }
        __syncthreads();

        if (kc < 127) {
            const float* xp = xg + (kc + 1) * 32;
            const float* wp = gw + (kc + 1) * 32;
#pragma unroll
            for (int j = 0; j < 4; j++) {
                xr[j] = *(const float4*)&xp[gidx[j]];
                wr[j] = *(const float4*)&wp[gidx[j]];
            }
        }

#pragma unroll
        for (int k = 0; k < 32; k += 4) {
            ulonglong2 B0 = *(const ulonglong2*)&Wb[(c0 + 0) * 32 + k];
            ulonglong2 B1 = *(const ulonglong2*)&Wb[(c0 + 1) * 32 + k];
            ulonglong2 B2 = *(const ulonglong2*)&Wb[(c0 + 2) * 32 + k];
            ulonglong2 B3 = *(const ulonglong2*)&Wb[(c0 + 3) * 32 + k];
#pragma unroll
            for (int r = 0; r < 8; r++) {
                ulonglong2 A = *(const ulonglong2*)&Xb[((row0 + r) * 32 + k) ^ aswz];
                fma2(acc[r][0], A.x, B0.x); fma2(acc[r][0], A.y, B0.y);
                fma2(acc[r][1], A.x, B1.x); fma2(acc[r][1], A.y, B1.y);
                fma2(acc[r][2], A.x, B2.x); fma2(acc[r][2], A.y, B2.y);
                fma2(acc[r][3], A.x, B3.x); fma2(acc[r][3], A.y, B3.y);
            }
        }
        // no trailing barrier: next iteration's stores target the other buffer,
        // and the barrier above guarantees prior reads of that buffer finished.
    }
    __syncthreads();

    // logits to smem, stride 68 (keeps float4 alignment, avoids pow2 conflicts)
    float* lg = smem;                    // 64*68 = 4352 floats
#pragma unroll
    for (int r = 0; r < 8; r++) {
        float4 v;
        v.x = ull_lo(acc[r][0]) + ull_hi(acc[r][0]);
        v.y = ull_lo(acc[r][1]) + ull_hi(acc[r][1]);
        v.z = ull_lo(acc[r][2]) + ull_hi(acc[r][2]);
        v.w = ull_lo(acc[r][3]) + ull_hi(acc[r][3]);
        *(float4*)&lg[(row0 + r) * 68 + c0] = v;
    }
    __syncthreads();

    // per-row softmax + top-2: warp w handles rows w*16 .. w*16+15
    const int lane = tid & 31;
    const int w = tid >> 5;
    for (int rr = 0; rr < 16; rr++) {
        const int r = w * 16 + rr;
        float2 lv = *(float2*)&lg[r * 68 + lane * 2];
        float v0 = lv.x, v1 = lv.y;

        float m = fmaxf(v0, v1);
#pragma unroll
        for (int off = 16; off; off >>= 1)
            m = fmaxf(m, __shfl_xor_sync(0xffffffffu, m, off));

        float e0 = expf(v0 - m), e1 = expf(v1 - m);
        float s = e0 + e1;
#pragma unroll
        for (int off = 16; off; off >>= 1)
            s += __shfl_xor_sync(0xffffffffu, s, off);
        float inv = 1.0f / s;

        const int gtok = rowBase + r;
        *(float2*)&probs_out[(size_t)gtok * N_EXP + lane * 2] =
            make_float2(e0 * inv, e1 * inv);

        // top-1 (ties -> lower index, matching jax top_k)
        float cv; int ci;
        if (v0 >= v1) { cv = v0; ci = lane * 2; } else { cv = v1; ci = lane * 2 + 1; }
#pragma unroll
        for (int off = 16; off; off >>= 1) {
            float ov = __shfl_xor_sync(0xffffffffu, cv, off);
            int   oi = __shfl_xor_sync(0xffffffffu, ci, off);
            if (ov > cv || (ov == cv && oi < ci)) { cv = ov; ci = oi; }
        }
        const float t1v = cv; const int t1i = ci;

        // top-2: lane holding t1i offers its other column
        if (lane * 2 == t1i)          { cv = v1; ci = lane * 2 + 1; }
        else if (lane * 2 + 1 == t1i) { cv = v0; ci = lane * 2; }
        else if (v0 >= v1)            { cv = v0; ci = lane * 2; }
        else                          { cv = v1; ci = lane * 2 + 1; }
#pragma unroll
        for (int off = 16; off; off >>= 1) {
            float ov = __shfl_xor_sync(0xffffffffu, cv, off);
            int   oi = __shfl_xor_sync(0xffffffffu, ci, off);
            if (ov > cv || (ov == cv && oi < ci)) { cv = ov; ci = oi; }
        }
        const float t2v = cv; const int t2i = ci;

        if (lane == 0) {
            float rr2 = expf(t2v - t1v);
            float inv2 = 1.0f / (1.0f + rr2);
            g_topk_idx[2 * gtok]     = t1i;
            g_topk_idx[2 * gtok + 1] = t2i;
            g_topk_val[2 * gtok]     = inv2;
            g_topk_val[2 * gtok + 1] = rr2 * inv2;
        }
    }
}

// ---------------------------------------------------------------------------
// Kernel 2: one block per expert. Ordered prefix count over the flat (N*K)
// assignment list (token-major, matching reference cumsum), scatter kept
// entries, record total count, deterministic column-sum of probs.
// ---------------------------------------------------------------------------
__global__ __launch_bounds__(256)
void scan_scatter_kernel(float* __restrict__ mask,
                         float* __restrict__ combine,
                         const float* __restrict__ probs) {
    const int e = blockIdx.x;
    const int tid = threadIdx.x;
    const int lane = tid & 31;
    const int w = tid >> 5;
    __shared__ int   wsum[8];
    __shared__ float fsum[8];

    int running = 0;
    for (int base = 0; base < N_TOK * TOPK; base += 256) {
        const int i = base + tid;
        const bool m = (g_topk_idx[i] == e);
        const unsigned bal = __ballot_sync(0xffffffffu, m);
        if (lane == 0) wsum[w] = __popc(bal);
        __syncthreads();
        int woff = 0, tot = 0;
#pragma unroll
        for (int j = 0; j < 8; j++) {
            int t = wsum[j];
            if (j < w) woff += t;
            tot += t;
        }
        if (m) {
            const int slot = running + woff + __popc(bal & ((1u << lane) - 1u));
            if (slot < CAP) {
                const int tok = i >> 1;
                const size_t o = (size_t)tok * (N_EXP * CAP) + e * CAP + slot;
                mask[o] = 1.0f;
                combine[o] = g_topk_val[i];
            }
        }
        running += tot;
        __syncthreads();
    }
    if (tid == 0) g_counts[e] = running;

    // deterministic column sum of probs[:, e]
    float s = 0.0f;
    for (int t = tid; t < N_TOK; t += 256)
        s += probs[(size_t)t * N_EXP + e];
#pragma unroll
    for (int off = 16; off; off >>= 1)
        s += __shfl_xor_sync(0xffffffffu, s, off);
    if (lane == 0) fsum[w] = s;
    __syncthreads();
    if (tid == 0) {
        float t = 0.0f;
#pragma unroll
        for (int j = 0; j < 8; j++) t += fsum[j];
        g_colsum[e] = t;
    }
}

// ---------------------------------------------------------------------------
// Kernel 3: load-balancing loss (scalar).
// ---------------------------------------------------------------------------
__global__ void loss_kernel(float* __restrict__ out_loss) {
    const int e = threadIdx.x;   // 64 threads
    __shared__ float sh[N_EXP];
    sh[e] = ((float)g_counts[e] / (float)(N_TOK * TOPK)) *
            (g_colsum[e] / (float)N_TOK);
    __syncthreads();
    if (e == 0) {
        float s = 0.0f;
#pragma unroll
        for (int j = 0; j < N_EXP; j++) s += sh[j];
        out_loss[0] = 0.01f * (float)N_EXP * s;
    }
}

// ---------------------------------------------------------------------------
extern "C" void kernel_launch(void* const* d_in, const int* in_sizes, int n_in,
                              void* d_out, int out_size) {
    const float* x  = (const float*)d_in[0];
    const float* gw = (const float*)d_in[1];
    if (n_in >= 2 && in_sizes[0] < in_sizes[1]) {  // robustness vs input ordering
        const float* t = x; x = gw; gw = t;
    }
    float* out = (float*)d_out;

    // layout: [dispatch_mask (N,E,C)] [combine_weights (N,E,C)] [probs (N,E)] [loss]
    float* mask    = out;
    float* combine = out + NEC;
    float* probs   = out + 2 * NEC;
    float* loss    = out + 2 * NEC + (size_t)N_TOK * N_EXP;

    // Lazily-created side stream + events (resource creation only; the
    // launched work is identical on every call).
    static cudaStream_t s_side = nullptr;
    static cudaEvent_t  s_ev0  = nullptr;
    static cudaEvent_t  s_ev1  = nullptr;
    if (s_side == nullptr) {
        cudaStreamCreateWithFlags(&s_side, cudaStreamNonBlocking);
        cudaEventCreateWithFlags(&s_ev0, cudaEventDisableTiming);
        cudaEventCreateWithFlags(&s_ev1, cudaEventDisableTiming);
    }

    // Fork: 671MB zero-fill of mask+combine overlaps the GEMM.
    cudaEventRecord(s_ev0, (cudaStream_t)0);
    cudaStreamWaitEvent(s_side, s_ev0, 0);
    cudaMemsetAsync(out, 0, 2 * NEC * sizeof(float), s_side);

    gemm_topk_kernel<<<N_TOK / 64, 128>>>(x, gw, probs);

    // Join: scatter writes into mask/combine must follow the memset.
    cudaEventRecord(s_ev1, s_side);
    cudaStreamWaitEvent((cudaStream_t)0, s_ev1, 0);

    scan_scatter_kernel<<<N_EXP, 256>>>(mask, combine, probs);
    loss_kernel<<<1, N_EXP>>>(loss);
}

// round 5
// speedup vs baseline: 1.4796x; 1.4796x over previous
#include <cuda_runtime.h>
#include <cstdint>

// Problem constants
#define N_TOK   8192
#define DIM     4096
#define N_EXP   64
#define TOPK    2
#define CAP     160           // ceil(1.25 * 8192 / 64)
#define NEC     ((size_t)N_TOK * N_EXP * CAP)   // 83,886,080

// Scratch (device globals; no allocation allowed)
__device__ int   g_topk_idx[N_TOK * TOPK];
__device__ float g_topk_val[N_TOK * TOPK];
__device__ int   g_counts[N_EXP];
__device__ float g_colsum[N_EXP];

// packed fp32x2 FMA (sm_103a FFMA2): d.lo += a.lo*b.lo, d.hi += a.hi*b.hi
__device__ __forceinline__ void fma2(unsigned long long& d,
                                     unsigned long long a,
                                     unsigned long long b) {
    asm("fma.rn.f32x2 %0, %1, %2, %0;" : "+l"(d) : "l"(a), "l"(b));
}
__device__ __forceinline__ float ull_lo(unsigned long long a) {
    return __uint_as_float((unsigned)(a & 0xffffffffu));
}
__device__ __forceinline__ float ull_hi(unsigned long long a) {
    return __uint_as_float((unsigned)(a >> 32));
}

// ---------------------------------------------------------------------------
// Kernel 1: GEMM (logits = x @ gate_w^T) + softmax (probs) + top-2.
// Grid 128 x 256 threads (8 warps/SM). Block tile 64 rows x 64 experts.
// Thread tile 4 rows x 4 cols; mapping rg=tid>>4 (rows rg*4..+3),
// cg=tid&15 (cols cg+{0,16,32,48}) makes every A-LDS.128 a 16-lane
// broadcast (1 crossbar cyc) and every B-LDS.128 a 2-phase read (2 cyc),
// pushing the kernel onto the fma pipe (model 63us, predict ~90us).
// Double-buffered smem, one barrier per 32-wide K chunk.
// ---------------------------------------------------------------------------
__global__ __launch_bounds__(256)
void gemm_topk_kernel(const float* __restrict__ x,
                      const float* __restrict__ gw,
                      float* __restrict__ probs_out) {
    __shared__ float smem[8192];         // 32KB: [buf0: X 2048 | W 2048][buf1]

    const int tid = threadIdx.x;
    const int rowBase = blockIdx.x * 64;
    const int rg = tid >> 4;             // 0..15 -> rows rg*4 .. rg*4+3
    const int cg = tid & 15;             // cols cg, cg+16, cg+32, cg+48
    const int row0 = rg * 4;
    const int swzA = (rg & 7) << 2;      // == ((row>>2)&7)<<2 for rows row0..row0+3
    const int swzB = (cg & 7) << 2;      // == ((col&7))<<2 for all 4 cols (16j keeps low bits)

    const float* xg = x + (size_t)rowBase * DIM;

    // staging: 2 float4 per thread per matrix per chunk (512 float4 each)
    int xoff[2], woff[2], gidx[2];
#pragma unroll
    for (int j = 0; j < 2; j++) {
        const int f = tid + j * 256;     // 0..511
        const int r = f >> 3;            // row/expert 0..63
        const int kq = (f & 7) * 4;      // float offset in 32-float row
        xoff[j] = (r * 32 + kq) ^ (((r >> 2) & 7) << 2);  // A swizzle: (row>>2)&7
        woff[j] = (r * 32 + kq) ^ ((r & 7) << 2);         // B swizzle: col&7
        gidx[j] = r * DIM + kq;
    }

    unsigned long long acc[4][4];
#pragma unroll
    for (int r = 0; r < 4; r++)
#pragma unroll
        for (int c = 0; c < 4; c++) acc[r][c] = 0ull;

    float4 xr[2], wr[2];
#pragma unroll
    for (int j = 0; j < 2; j++) {        // prologue: chunk 0
        xr[j] = *(const float4*)&xg[gidx[j]];
        wr[j] = *(const float4*)&gw[gidx[j]];
    }

#pragma unroll 1
    for (int kc = 0; kc < 128; kc++) {
        float* Xb = smem + (kc & 1) * 4096;
        float* Wb = Xb + 2048;
#pragma unroll
        for (int j = 0; j < 2; j++) {
            *(float4*)&Xb[xoff[j]] = xr[j];
            *(float4*)&Wb[woff[j]] = wr[j];
        }
        __syncthreads();

        if (kc < 127) {
            const float* xp = xg + (kc + 1) * 32;
            const float* wp = gw + (kc + 1) * 32;
#pragma unroll
            for (int j = 0; j < 2; j++) {
                xr[j] = *(const float4*)&xp[gidx[j]];
                wr[j] = *(const float4*)&wp[gidx[j]];
            }
        }

#pragma unroll
        for (int k = 0; k < 32; k += 4) {
            // B: 4 cols, 16 distinct addrs/warp, 2-way banked -> 2 cyc each
            ulonglong2 B0 = *(const ulonglong2*)&Wb[((cg +  0) * 32 + k) ^ swzB];
            ulonglong2 B1 = *(const ulonglong2*)&Wb[((cg + 16) * 32 + k) ^ swzB];
            ulonglong2 B2 = *(const ulonglong2*)&Wb[((cg + 32) * 32 + k) ^ swzB];
            ulonglong2 B3 = *(const ulonglong2*)&Wb[((cg + 48) * 32 + k) ^ swzB];
#pragma unroll
            for (int r = 0; r < 4; r++) {
                // A: 16-lane broadcast, 2 distinct addrs on distinct quads -> 1 cyc
                ulonglong2 A = *(const ulonglong2*)&Xb[((row0 + r) * 32 + k) ^ swzA];
                fma2(acc[r][0], A.x, B0.x); fma2(acc[r][0], A.y, B0.y);
                fma2(acc[r][1], A.x, B1.x); fma2(acc[r][1], A.y, B1.y);
                fma2(acc[r][2], A.x, B2.x); fma2(acc[r][2], A.y, B2.y);
                fma2(acc[r][3], A.x, B3.x); fma2(acc[r][3], A.y, B3.y);
            }
        }
        // no trailing barrier needed: next stores hit the other buffer and the
        // top-of-loop barrier proves all reads of that buffer completed.
    }
    __syncthreads();

    // logits to smem, stride 68
    float* lg = smem;                    // 64*68 = 4352 floats
#pragma unroll
    for (int r = 0; r < 4; r++) {
#pragma unroll
        for (int c = 0; c < 4; c++) {
            lg[(row0 + r) * 68 + cg + c * 16] =
                ull_lo(acc[r][c]) + ull_hi(acc[r][c]);
        }
    }
    __syncthreads();

    // per-row softmax + top-2: warp w handles rows w*8 .. w*8+7
    const int lane = tid & 31;
    const int w = tid >> 5;
    for (int rr = 0; rr < 8; rr++) {
        const int r = w * 8 + rr;
        float2 lv = *(float2*)&lg[r * 68 + lane * 2];
        float v0 = lv.x, v1 = lv.y;

        float m = fmaxf(v0, v1);
#pragma unroll
        for (int off = 16; off; off >>= 1)
            m = fmaxf(m, __shfl_xor_sync(0xffffffffu, m, off));

        float e0 = expf(v0 - m), e1 = expf(v1 - m);
        float s = e0 + e1;
#pragma unroll
        for (int off = 16; off; off >>= 1)
            s += __shfl_xor_sync(0xffffffffu, s, off);
        float inv = 1.0f / s;

        const int gtok = rowBase + r;
        *(float2*)&probs_out[(size_t)gtok * N_EXP + lane * 2] =
            make_float2(e0 * inv, e1 * inv);

        // top-1 (ties -> lower index, matching jax top_k)
        float cv; int ci;
        if (v0 >= v1) { cv = v0; ci = lane * 2; } else { cv = v1; ci = lane * 2 + 1; }
#pragma unroll
        for (int off = 16; off; off >>= 1) {
            float ov = __shfl_xor_sync(0xffffffffu, cv, off);
            int   oi = __shfl_xor_sync(0xffffffffu, ci, off);
            if (ov > cv || (ov == cv && oi < ci)) { cv = ov; ci = oi; }
        }
        const float t1v = cv; const int t1i = ci;

        // top-2: lane holding t1i offers its other column
        if (lane * 2 == t1i)          { cv = v1; ci = lane * 2 + 1; }
        else if (lane * 2 + 1 == t1i) { cv = v0; ci = lane * 2; }
        else if (v0 >= v1)            { cv = v0; ci = lane * 2; }
        else                          { cv = v1; ci = lane * 2 + 1; }
#pragma unroll
        for (int off = 16; off; off >>= 1) {
            float ov = __shfl_xor_sync(0xffffffffu, cv, off);
            int   oi = __shfl_xor_sync(0xffffffffu, ci, off);
            if (ov > cv || (ov == cv && oi < ci)) { cv = ov; ci = oi; }
        }
        const float t2v = cv; const int t2i = ci;

        if (lane == 0) {
            float rr2 = expf(t2v - t1v);
            float inv2 = 1.0f / (1.0f + rr2);
            g_topk_idx[2 * gtok]     = t1i;
            g_topk_idx[2 * gtok + 1] = t2i;
            g_topk_val[2 * gtok]     = inv2;
            g_topk_val[2 * gtok + 1] = rr2 * inv2;
        }
    }
}

// ---------------------------------------------------------------------------
// Kernel 2: one block per expert. Ordered prefix count over the flat (N*K)
// assignment list (token-major, matching reference cumsum), scatter kept
// entries, record total count, deterministic column-sum of probs.
// ---------------------------------------------------------------------------
__global__ __launch_bounds__(256)
void scan_scatter_kernel(float* __restrict__ mask,
                         float* __restrict__ combine,
                         const float* __restrict__ probs) {
    const int e = blockIdx.x;
    const int tid = threadIdx.x;
    const int lane = tid & 31;
    const int w = tid >> 5;
    __shared__ int   wsum[8];
    __shared__ float fsum[8];

    int running = 0;
    for (int base = 0; base < N_TOK * TOPK; base += 256) {
        const int i = base + tid;
        const bool m = (g_topk_idx[i] == e);
        const unsigned bal = __ballot_sync(0xffffffffu, m);
        if (lane == 0) wsum[w] = __popc(bal);
        __syncthreads();
        int woff = 0, tot = 0;
#pragma unroll
        for (int j = 0; j < 8; j++) {
            int t = wsum[j];
            if (j < w) woff += t;
            tot += t;
        }
        if (m) {
            const int slot = running + woff + __popc(bal & ((1u << lane) - 1u));
            if (slot < CAP) {
                const int tok = i >> 1;
                const size_t o = (size_t)tok * (N_EXP * CAP) + e * CAP + slot;
                mask[o] = 1.0f;
                combine[o] = g_topk_val[i];
            }
        }
        running += tot;
        __syncthreads();
    }
    if (tid == 0) g_counts[e] = running;

    // deterministic column sum of probs[:, e]
    float s = 0.0f;
    for (int t = tid; t < N_TOK; t += 256)
        s += probs[(size_t)t * N_EXP + e];
#pragma unroll
    for (int off = 16; off; off >>= 1)
        s += __shfl_xor_sync(0xffffffffu, s, off);
    if (lane == 0) fsum[w] = s;
    __syncthreads();
    if (tid == 0) {
        float t = 0.0f;
#pragma unroll
        for (int j = 0; j < 8; j++) t += fsum[j];
        g_colsum[e] = t;
    }
}

// ---------------------------------------------------------------------------
// Kernel 3: load-balancing loss (scalar).
// ---------------------------------------------------------------------------
__global__ void loss_kernel(float* __restrict__ out_loss) {
    const int e = threadIdx.x;   // 64 threads
    __shared__ float sh[N_EXP];
    sh[e] = ((float)g_counts[e] / (float)(N_TOK * TOPK)) *
            (g_colsum[e] / (float)N_TOK);
    __syncthreads();
    if (e == 0) {
        float s = 0.0f;
#pragma unroll
        for (int j = 0; j < N_EXP; j++) s += sh[j];
        out_loss[0] = 0.01f * (float)N_EXP * s;
    }
}

// ---------------------------------------------------------------------------
extern "C" void kernel_launch(void* const* d_in, const int* in_sizes, int n_in,
                              void* d_out, int out_size) {
    const float* x  = (const float*)d_in[0];
    const float* gw = (const float*)d_in[1];
    if (n_in >= 2 && in_sizes[0] < in_sizes[1]) {  // robustness vs input ordering
        const float* t = x; x = gw; gw = t;
    }
    float* out = (float*)d_out;

    // layout: [dispatch_mask (N,E,C)] [combine_weights (N,E,C)] [probs (N,E)] [loss]
    float* mask    = out;
    float* combine = out + NEC;
    float* probs   = out + 2 * NEC;
    float* loss    = out + 2 * NEC + (size_t)N_TOK * N_EXP;

    // Plain sequential on the capture stream (R3's fork-stream regressed).
    cudaMemsetAsync(out, 0, 2 * NEC * sizeof(float));
    gemm_topk_kernel<<<N_TOK / 64, 256>>>(x, gw, probs);
    scan_scatter_kernel<<<N_EXP, 256>>>(mask, combine, probs);
    loss_kernel<<<1, N_EXP>>>(loss);
}